// round 15
// baseline (speedup 1.0000x reference)
#include <cuda_runtime.h>

#define BSZ  16
#define SEQ  4096
#define D    64
#define NH   64
#define L    64
#define NC   64      // SEQ / L
#define DOUT 64
#define NG   8       // groups of chunks
#define GS   8       // chunks per group

// ---------------- scratch (static device globals; no runtime allocation) ----------------
__device__ float g_xT[D*BSZ*SEQ];        // xT[d][b][t]
__device__ float g_Wv[L*D*NH];           // Wv[j][d][n] = (dA^(L-1-j) dB_d)[n]
__device__ float g_Rp[(L+1)*D*NH];       // Rp[i][d][n] = (Cp_d dA^i)[n]
__device__ float g_Keff[L*D];            // Keff[i][d]  = Rp[i][d]·dB_d (+Dp at i==0)
__device__ float g_MpT[NH*NH];           // MpT[m][n]   = (dA^L)[n][m]
__device__ float g_M8T[NH*NH];           // [m*64+n]    = (M^8)[n][m]
__device__ float g_G[NC*D*BSZ*NH];       // G[c][d][b][n]
__device__ float g_y[D*BSZ*SEQ];         // y[d][b][t]: k_scan writes cross term, k_y adds conv

// ---------------- K0: per-channel tables + dA^L -----------------------------------------
__global__ __launch_bounds__(64) void k_tables(const float* __restrict__ dA,
                                               const float* __restrict__ dB,
                                               const float* __restrict__ Cp,
                                               const float* __restrict__ Dp)
{
    __shared__ float sA[NH*NH];   // sA[m*NH+n]  = dA[m][n]
    __shared__ float sAT[NH*NH];  // sAT[m*NH+n] = dA[n][m]
    int tid = threadIdx.x;
    for (int i = tid; i < NH*NH; i += 64) {
        float v = dA[i];                       // i = n*NH + m
        sA[i] = v;
        sAT[(i & 63)*NH + (i >> 6)] = v;
    }
    __syncthreads();

    int bid = blockIdx.x;
    int n = tid;
    if (bid < D) {
        int d = bid;
        __shared__ float sv[NH], sr[NH], rbuf[NH];
        float dbv = dB[d*NH + n];
        sv[n]  = dbv;                          // Wv[L-1] = dB_d
        float rv = Cp[d*NH + n];
        sr[n]  = rv;                           // Rp[0]   = Cp_d
        rbuf[n] = rv * dbv;
        __syncthreads();

        g_Wv[(L-1)*D*NH + d*NH + n] = dbv;
        g_Rp[0*D*NH + d*NH + n]     = rv;
        if (tid < 32) {
            float s = rbuf[tid] + rbuf[tid+32];
            #pragma unroll
            for (int o = 16; o > 0; o >>= 1) s += __shfl_down_sync(0xffffffffu, s, o);
            if (tid == 0) g_Keff[0*D + d] = s + Dp[d];
        }
        for (int i = 1; i <= L; i++) {
            float vn = 0.f, rn = 0.f;
            #pragma unroll 16
            for (int m = 0; m < NH; m++) {
                vn += sAT[m*NH + n] * sv[m];   // vn = (dA * v)[n]
                rn += sA [m*NH + n] * sr[m];   // rn = (r * dA)[n]
            }
            __syncthreads();
            sv[n] = vn; sr[n] = rn; rbuf[n] = rn * dbv;
            __syncthreads();
            if (i <= L-1) g_Wv[(L-1-i)*D*NH + d*NH + n] = vn;
            g_Rp[i*D*NH + d*NH + n] = rn;
            if (i <= L-1 && tid < 32) {
                float s = rbuf[tid] + rbuf[tid+32];
                #pragma unroll
                for (int o = 16; o > 0; o >>= 1) s += __shfl_down_sync(0xffffffffu, s, o);
                if (tid == 0) g_Keff[i*D + d] = s;
            }
        }
    } else {
        // column m of dA^L
        int m = bid - D;
        __shared__ float sc[NH];
        sc[n] = (n == m) ? 1.f : 0.f;
        __syncthreads();
        for (int i = 0; i < L; i++) {
            float vn = 0.f;
            #pragma unroll 16
            for (int k = 0; k < NH; k++) vn += sAT[k*NH + n] * sc[k];
            __syncthreads();
            sc[n] = vn;
            __syncthreads();
        }
        g_MpT[m*NH + n] = sc[n];               // = (dA^L)[n][m]
    }
}

// ---------------- KP: M^8 only (transposed: g_M8T[m*64+n] = M^8[n][m]) -------------------
__global__ __launch_bounds__(64) void k_pow()
{
    __shared__ float sMT[NH*NH];   // [k*64+n] = M[n][k]
    __shared__ float sc[NH];
    int m = blockIdx.x, n = threadIdx.x;
    for (int i = n; i < NH*NH; i += 64) sMT[i] = g_MpT[i];
    sc[n] = (n == m) ? 1.f : 0.f;
    __syncthreads();
    for (int i = 0; i < 8; i++) {
        float vn = 0.f;
        #pragma unroll 16
        for (int kk = 0; kk < NH; kk++) vn += sMT[kk*NH + n] * sc[kk];
        __syncthreads();
        sc[n] = vn;
        __syncthreads();
    }
    g_M8T[m*NH + n] = sc[n];
}

// ---------------- KT: transpose x (B,S,D) -> xT (D,B,S) ---------------------------------
__global__ __launch_bounds__(256) void k_transpose(const float* __restrict__ x)
{
    __shared__ float tile[64][65];
    int b = blockIdx.x, t0 = blockIdx.y << 6;
    int tid = threadIdx.x;
    for (int i = tid; i < 4096; i += 256) {
        int tt = i >> 6, d = i & 63;
        tile[tt][d] = x[(b*SEQ + t0 + tt)*D + d];
    }
    __syncthreads();
    for (int i = tid; i < 4096; i += 256) {
        int d = i >> 6, tt = i & 63;
        g_xT[(d*BSZ + b)*SEQ + t0 + tt] = tile[tt][d];
    }
}

// ---------------- K1: G[c][d][b][:] = sum_j Wv[j][d][:] * u[c,j,d,b] ---------------------
#define UP 20
__global__ __launch_bounds__(256) void k_G()
{
    __shared__ float sWv[L*NH];        // sWv[j*NH + n]
    __shared__ float sU[256*UP];       // sU[t*UP + b], t = cc*64+j (4 chunks)
    int d = blockIdx.x, cb4 = blockIdx.y;
    int tid = threadIdx.x;
    for (int i = tid; i < L*NH; i += 256)
        sWv[i] = g_Wv[(i >> 6)*(D*NH) + d*NH + (i & 63)];
    for (int i = tid; i < 4096; i += 256) {
        int b = i >> 8, t = i & 255;
        sU[t*UP + b] = g_xT[(d*BSZ + b)*SEQ + (cb4 << 8) + t];
    }
    __syncthreads();

    int nq = tid & 15, cbq = tid >> 4;
    int n0 = nq << 2;
    int cc = cbq >> 2, b0 = (cbq & 3) << 2;
    float acc[4][4];
    #pragma unroll
    for (int bi = 0; bi < 4; bi++)
        #pragma unroll
        for (int ni = 0; ni < 4; ni++) acc[bi][ni] = 0.f;

    #pragma unroll 8
    for (int j = 0; j < L; j++) {
        float4 w = *(const float4*)&sWv[j*NH + n0];
        float4 u = *(const float4*)&sU[(cc*64 + j)*UP + b0];
        acc[0][0] += u.x*w.x; acc[0][1] += u.x*w.y; acc[0][2] += u.x*w.z; acc[0][3] += u.x*w.w;
        acc[1][0] += u.y*w.x; acc[1][1] += u.y*w.y; acc[1][2] += u.y*w.z; acc[1][3] += u.y*w.w;
        acc[2][0] += u.z*w.x; acc[2][1] += u.z*w.y; acc[2][2] += u.z*w.z; acc[2][3] += u.z*w.w;
        acc[3][0] += u.w*w.x; acc[3][1] += u.w*w.y; acc[3][2] += u.w*w.z; acc[3][3] += u.w*w.w;
    }
    int c = (cb4 << 2) + cc;
    #pragma unroll
    for (int bi = 0; bi < 4; bi++) {
        float4 o = make_float4(acc[bi][0], acc[bi][1], acc[bi][2], acc[bi][3]);
        *(float4*)&g_G[((c*D + d)*BSZ + b0 + bi)*NH + n0] = o;
    }
}

// ---------------- K2: fused scan per (d,b): local scan -> carry scan -> rescan+cross -----
// Block = one (d,b) pair. Warp g owns chunk-group g. All state stays in regs/smem;
// emits the cross-term y_cross[r] = Rp[r+1]·H_c straight to g_y. H never hits HBM.
#define SCAN_SMEM (16384 + 16384 + 16640 + 16384 + 2048 + 2048)   // 69888 B
__global__ __launch_bounds__(256) void k_scan()
{
    extern __shared__ char smem_raw[];
    float2* sM  = (float2*)(smem_raw);                    // [2048]: {M[n][m], M[n+32][m]}
    float2* sM8 = (float2*)(smem_raw + 16384);            // [2048]: same for M^8
    float*  sRp = (float*) (smem_raw + 32768);            // [64*65]: sRp[m*65+r] = Rp[r+1][d][m]
    float*  sG  = (float*) (smem_raw + 49408);            // [4096]:  sG[c*64+n]
    float*  sS  = (float*) (smem_raw + 65792);            // [512]:   group sums
    float*  sC  = (float*) (smem_raw + 67840);            // [512]:   carries

    int tid = threadIdx.x, lane = tid & 31, w = tid >> 5;
    int bid = blockIdx.x;
    int d = bid >> 4, b = bid & 15;

    for (int i = tid; i < 2048; i += 256) {
        int m = i >> 5, nn = i & 31;
        sM[i]  = make_float2(g_MpT[m*NH + nn], g_MpT[m*NH + nn + 32]);
        sM8[i] = make_float2(g_M8T[m*NH + nn], g_M8T[m*NH + nn + 32]);
    }
    for (int i = tid; i < 4096; i += 256) {
        int r = i >> 6, m = i & 63;
        sRp[m*65 + r] = g_Rp[((r + 1)*D + d)*NH + m];
    }
    for (int i = tid; i < 4096; i += 256) {
        int c = i >> 6, n = i & 63;
        sG[i] = g_G[((c*D + d)*BSZ + b)*NH + n];
    }
    __syncthreads();

    // Phase A: local scan of group w (8 chunks), h starts at 0; emit group sum.
    {
        float h0 = 0.f, h1 = 0.f;
        for (int k = 0; k < GS; k++) {
            int c = w*GS + k;
            float g0 = sG[c*64 + lane], g1 = sG[c*64 + 32 + lane];
            float n0 = 0.f, n1 = 0.f;
            #pragma unroll
            for (int m = 0; m < 32; m++) {
                float hm = __shfl_sync(0xffffffffu, h0, m);
                float2 mm = sM[m*32 + lane];
                n0 += mm.x*hm; n1 += mm.y*hm;
            }
            #pragma unroll
            for (int m = 0; m < 32; m++) {
                float hm = __shfl_sync(0xffffffffu, h1, m);
                float2 mm = sM[(m + 32)*32 + lane];
                n0 += mm.x*hm; n1 += mm.y*hm;
            }
            h0 = n0 + g0; h1 = n1 + g1;
        }
        sS[w*64 + lane] = h0;  sS[w*64 + 32 + lane] = h1;
    }
    __syncthreads();

    // Phase B: warp 0 scans the 8 group carries: C[g+1] = M^8 C[g] + S[g].
    if (w == 0) {
        float c0 = 0.f, c1 = 0.f;
        for (int g = 0; g < NG; g++) {
            sC[g*64 + lane] = c0;  sC[g*64 + 32 + lane] = c1;
            float s0 = sS[g*64 + lane], s1 = sS[g*64 + 32 + lane];
            float n0 = 0.f, n1 = 0.f;
            #pragma unroll
            for (int m = 0; m < 32; m++) {
                float hm = __shfl_sync(0xffffffffu, c0, m);
                float2 mm = sM8[m*32 + lane];
                n0 += mm.x*hm; n1 += mm.y*hm;
            }
            #pragma unroll
            for (int m = 0; m < 32; m++) {
                float hm = __shfl_sync(0xffffffffu, c1, m);
                float2 mm = sM8[(m + 32)*32 + lane];
                n0 += mm.x*hm; n1 += mm.y*hm;
            }
            c0 = n0 + s0; c1 = n1 + s1;
        }
    }
    __syncthreads();

    // Phase C: rescan seeded with carry; per chunk emit y_cross then advance state.
    {
        float h0 = sC[w*64 + lane], h1 = sC[w*64 + 32 + lane];
        int ybase = (d*BSZ + b)*SEQ;
        for (int k = 0; k < GS; k++) {
            int c = w*GS + k;
            float y0 = 0.f, y1 = 0.f;
            #pragma unroll
            for (int m = 0; m < 32; m++) {
                float hm = __shfl_sync(0xffffffffu, h0, m);
                y0 += sRp[m*65 + lane]      * hm;
                y1 += sRp[m*65 + lane + 32] * hm;
            }
            #pragma unroll
            for (int m = 0; m < 32; m++) {
                float hm = __shfl_sync(0xffffffffu, h1, m);
                y0 += sRp[(m + 32)*65 + lane]      * hm;
                y1 += sRp[(m + 32)*65 + lane + 32] * hm;
            }
            g_y[ybase + c*64 + lane]      = y0;
            g_y[ybase + c*64 + 32 + lane] = y1;
            if (k == GS-1) break;
            float g0 = sG[c*64 + lane], g1 = sG[c*64 + 32 + lane];
            float n0 = 0.f, n1 = 0.f;
            #pragma unroll
            for (int m = 0; m < 32; m++) {
                float hm = __shfl_sync(0xffffffffu, h0, m);
                float2 mm = sM[m*32 + lane];
                n0 += mm.x*hm; n1 += mm.y*hm;
            }
            #pragma unroll
            for (int m = 0; m < 32; m++) {
                float hm = __shfl_sync(0xffffffffu, h1, m);
                float2 mm = sM[(m + 32)*32 + lane];
                n0 += mm.x*hm; n1 += mm.y*hm;
            }
            h0 = n0 + g0; h1 = n1 + g1;
        }
    }
}

// ---------------- K3: conv-only y update: g_y += causal conv of u with Keff --------------
__global__ __launch_bounds__(256) void k_y()
{
    __shared__ float sKp[128];         // zero-padded causal kernel
    __shared__ float sUc[2][L*UP];     // per-half chunk input [j*UP + b]
    int d = blockIdx.x, c0 = blockIdx.y << 2, tid = threadIdx.x;
    int half = tid >> 7, ltid = tid & 127;

    if (tid < 127) sKp[tid] = (tid < 63) ? 0.f : g_Keff[(tid - 63)*D + d];
    __syncthreads();

    for (int pass = 0; pass < 2; pass++) {
        int c = c0 + pass*2 + half;
        for (int i = ltid; i < 1024; i += 128) {
            int b = i >> 6, j = i & 63;
            sUc[half][j*UP + b] = g_xT[(d*BSZ + b)*SEQ + (c << 6) + j];
        }
        __syncthreads();

        int rq = ltid & 31, bq = ltid >> 5;
        int r0 = rq << 1, b0 = bq << 2;
        float acc[2][4];
        #pragma unroll
        for (int bi = 0; bi < 4; bi++) {          // init from cross term written by k_scan
            float2 v = *(const float2*)&g_y[(d*BSZ + b0 + bi)*SEQ + (c << 6) + r0];
            acc[0][bi] = v.x; acc[1][bi] = v.y;
        }

        #pragma unroll 8
        for (int j = 0; j < L; j++) {              // intra-chunk conv (zero-padded kernel)
            float k0 = sKp[63 + r0 - j];
            float k1 = sKp[64 + r0 - j];
            float4 u = *(const float4*)&sUc[half][j*UP + b0];
            acc[0][0] += k0*u.x; acc[0][1] += k0*u.y; acc[0][2] += k0*u.z; acc[0][3] += k0*u.w;
            acc[1][0] += k1*u.x; acc[1][1] += k1*u.y; acc[1][2] += k1*u.z; acc[1][3] += k1*u.w;
        }
        #pragma unroll
        for (int bi = 0; bi < 4; bi++) {
            float2 o = make_float2(acc[0][bi], acc[1][bi]);
            *(float2*)&g_y[(d*BSZ + b0 + bi)*SEQ + (c << 6) + r0] = o;
        }
        __syncthreads();
    }
}

// ---------------- K4: out[b][t][:] = y[:, b, t]·W^T + bias -------------------------------
#define WP 68
__global__ __launch_bounds__(256) void k_mix(const float* __restrict__ Wm,
                                             const float* __restrict__ bias,
                                             float* __restrict__ out)
{
    __shared__ float sW[D*WP];         // sW[d*WP + o] = W[o][d]
    __shared__ float sy[D*WP];         // sy[d*WP + tt]
    int b = blockIdx.x, t0 = blockIdx.y << 6, tid = threadIdx.x;
    for (int i = tid; i < 4096; i += 256) {
        int o = i >> 6, dd = i & 63;
        sW[dd*WP + o] = Wm[o*D + dd];
    }
    for (int i = tid; i < 4096; i += 256) {
        int dd = i >> 6, tt = i & 63;
        sy[dd*WP + tt] = g_y[(dd*BSZ + b)*SEQ + t0 + tt];
    }
    __syncthreads();

    int tq = tid & 15, oq = tid >> 4;
    int tl0 = tq << 2, o0 = oq << 2;
    float acc[4][4];
    #pragma unroll
    for (int ti = 0; ti < 4; ti++)
        #pragma unroll
        for (int oi = 0; oi < 4; oi++) acc[ti][oi] = 0.f;

    #pragma unroll 8
    for (int dd = 0; dd < D; dd++) {
        float4 wv = *(const float4*)&sW[dd*WP + o0];
        float4 yv = *(const float4*)&sy[dd*WP + tl0];
        acc[0][0] += yv.x*wv.x; acc[0][1] += yv.x*wv.y; acc[0][2] += yv.x*wv.z; acc[0][3] += yv.x*wv.w;
        acc[1][0] += yv.y*wv.x; acc[1][1] += yv.y*wv.y; acc[1][2] += yv.y*wv.z; acc[1][3] += yv.y*wv.w;
        acc[2][0] += yv.z*wv.x; acc[2][1] += yv.z*wv.y; acc[2][2] += yv.z*wv.z; acc[2][3] += yv.z*wv.w;
        acc[3][0] += yv.w*wv.x; acc[3][1] += yv.w*wv.y; acc[3][2] += yv.w*wv.z; acc[3][3] += yv.w*wv.w;
    }
    float4 bv = *(const float4*)&bias[o0];
    #pragma unroll
    for (int ti = 0; ti < 4; ti++) {
        float4 o = make_float4(acc[ti][0] + bv.x, acc[ti][1] + bv.y,
                               acc[ti][2] + bv.z, acc[ti][3] + bv.w);
        *(float4*)&out[(b*SEQ + t0 + tl0 + ti)*DOUT + o0] = o;
    }
}

// ---------------- launch -----------------------------------------------------------------
extern "C" void kernel_launch(void* const* d_in, const int* in_sizes, int n_in,
                              void* d_out, int out_size)
{
    const float* x    = (const float*)d_in[0];
    const float* dA   = (const float*)d_in[1];
    const float* dB   = (const float*)d_in[2];
    const float* Cp   = (const float*)d_in[3];
    const float* Dp   = (const float*)d_in[4];
    const float* Wm   = (const float*)d_in[5];
    const float* bias = (const float*)d_in[6];
    float* out = (float*)d_out;

    cudaFuncSetAttribute(k_scan, cudaFuncAttributeMaxDynamicSharedMemorySize, SCAN_SMEM);

    k_tables   <<<128, 64>>>(dA, dB, Cp, Dp);
    k_pow      <<<64, 64>>>();
    k_transpose<<<dim3(BSZ, SEQ/64), 256>>>(x);
    k_G        <<<dim3(D, NC/4), 256>>>();
    k_scan     <<<1024, 256, SCAN_SMEM>>>();
    k_y        <<<dim3(D, NC/4), 256>>>();
    k_mix      <<<dim3(BSZ, SEQ/64), 256>>>(Wm, bias, out);
}

// round 16
// speedup vs baseline: 1.3236x; 1.3236x over previous
#include <cuda_runtime.h>

#define BSZ  16
#define SEQ  4096
#define D    64
#define NH   64
#define L    64
#define NC   64      // SEQ / L
#define DOUT 64
#define NG   8       // groups of chunks
#define GS   8       // chunks per group

// ---------------- scratch (static device globals; no runtime allocation) ----------------
__device__ float g_xT[D*BSZ*SEQ];        // xT[d][b][t]
__device__ float g_Wv[L*D*NH];           // Wv[j][d][n] = (dA^(L-1-j) dB_d)[n]
__device__ float g_Rp[(L+1)*D*NH];       // Rp[i][d][n] = (Cp_d dA^i)[n]
__device__ float g_Keff[L*D];            // Keff[i][d]  = Rp[i][d]·dB_d (+Dp at i==0)
__device__ float g_MpT[NH*NH];           // MpT[m][n]   = (dA^L)[n][m]
__device__ float g_M8T[NH*NH];           // [m*64+n]    = (M^8)[n][m]
__device__ float g_G[NC*D*BSZ*NH];       // G[c][pair][n],  pair = d*16+b
__device__ float g_H[NC*D*BSZ*NH];       // corrected H[c][pair][n] (state entering chunk c)
__device__ float g_S[NG*D*BSZ*NH];       // S[g][pair][n] = group sum
__device__ float g_C[NG*D*BSZ*NH];       // C[g][pair][n] = carry entering group g
__device__ float g_y[D*BSZ*SEQ];         // y[d][b][t] (pre-mix)

// ---------------- K0: per-channel tables + dA^L -----------------------------------------
__global__ __launch_bounds__(64) void k_tables(const float* __restrict__ dA,
                                               const float* __restrict__ dB,
                                               const float* __restrict__ Cp,
                                               const float* __restrict__ Dp)
{
    __shared__ float sA[NH*NH];   // sA[m*NH+n]  = dA[m][n]
    __shared__ float sAT[NH*NH];  // sAT[m*NH+n] = dA[n][m]
    int tid = threadIdx.x;
    for (int i = tid; i < NH*NH; i += 64) {
        float v = dA[i];                       // i = n*NH + m
        sA[i] = v;
        sAT[(i & 63)*NH + (i >> 6)] = v;
    }
    __syncthreads();

    int bid = blockIdx.x;
    int n = tid;
    if (bid < D) {
        int d = bid;
        __shared__ float sv[NH], sr[NH], rbuf[NH];
        float dbv = dB[d*NH + n];
        sv[n]  = dbv;                          // Wv[L-1] = dB_d
        float rv = Cp[d*NH + n];
        sr[n]  = rv;                           // Rp[0]   = Cp_d
        rbuf[n] = rv * dbv;
        __syncthreads();

        g_Wv[(L-1)*D*NH + d*NH + n] = dbv;
        g_Rp[0*D*NH + d*NH + n]     = rv;
        if (tid < 32) {
            float s = rbuf[tid] + rbuf[tid+32];
            #pragma unroll
            for (int o = 16; o > 0; o >>= 1) s += __shfl_down_sync(0xffffffffu, s, o);
            if (tid == 0) g_Keff[0*D + d] = s + Dp[d];
        }
        for (int i = 1; i <= L; i++) {
            float vn = 0.f, rn = 0.f;
            #pragma unroll 16
            for (int m = 0; m < NH; m++) {
                vn += sAT[m*NH + n] * sv[m];   // vn = (dA * v)[n]
                rn += sA [m*NH + n] * sr[m];   // rn = (r * dA)[n]
            }
            __syncthreads();
            sv[n] = vn; sr[n] = rn; rbuf[n] = rn * dbv;
            __syncthreads();
            if (i <= L-1) g_Wv[(L-1-i)*D*NH + d*NH + n] = vn;
            g_Rp[i*D*NH + d*NH + n] = rn;
            if (i <= L-1 && tid < 32) {
                float s = rbuf[tid] + rbuf[tid+32];
                #pragma unroll
                for (int o = 16; o > 0; o >>= 1) s += __shfl_down_sync(0xffffffffu, s, o);
                if (tid == 0) g_Keff[i*D + d] = s;
            }
        }
    } else {
        // column m of dA^L
        int m = bid - D;
        __shared__ float sc[NH];
        sc[n] = (n == m) ? 1.f : 0.f;
        __syncthreads();
        for (int i = 0; i < L; i++) {
            float vn = 0.f;
            #pragma unroll 16
            for (int k = 0; k < NH; k++) vn += sAT[k*NH + n] * sc[k];
            __syncthreads();
            sc[n] = vn;
            __syncthreads();
        }
        g_MpT[m*NH + n] = sc[n];               // = (dA^L)[n][m]
    }
}

// ---------------- KP: M^8 only (transposed: g_M8T[m*64+n] = M^8[n][m]) -------------------
__global__ __launch_bounds__(64) void k_pow()
{
    __shared__ float sMT[NH*NH];   // [k*64+n] = M[n][k]
    __shared__ float sc[NH];
    int m = blockIdx.x, n = threadIdx.x;
    for (int i = n; i < NH*NH; i += 64) sMT[i] = g_MpT[i];
    sc[n] = (n == m) ? 1.f : 0.f;
    __syncthreads();
    for (int i = 0; i < 8; i++) {
        float vn = 0.f;
        #pragma unroll 16
        for (int kk = 0; kk < NH; kk++) vn += sMT[kk*NH + n] * sc[kk];
        __syncthreads();
        sc[n] = vn;
        __syncthreads();
    }
    g_M8T[m*NH + n] = sc[n];
}

// ---------------- KT: transpose x (B,S,D) -> xT (D,B,S) ---------------------------------
__global__ __launch_bounds__(256) void k_transpose(const float* __restrict__ x)
{
    __shared__ float tile[64][65];
    int b = blockIdx.x, t0 = blockIdx.y << 6;
    int tid = threadIdx.x;
    for (int i = tid; i < 4096; i += 256) {
        int tt = i >> 6, d = i & 63;
        tile[tt][d] = x[(b*SEQ + t0 + tt)*D + d];
    }
    __syncthreads();
    for (int i = tid; i < 4096; i += 256) {
        int d = i >> 6, tt = i & 63;
        g_xT[(d*BSZ + b)*SEQ + t0 + tt] = tile[tt][d];
    }
}

// ---------------- K1: G[c][d][b][:] = sum_j Wv[j][d][:] * u[c,j,d,b] ---------------------
#define UP 20
__global__ __launch_bounds__(256) void k_G()
{
    __shared__ float sWv[L*NH];        // sWv[j*NH + n]
    __shared__ float sU[256*UP];       // sU[t*UP + b], t = cc*64+j (4 chunks)
    int d = blockIdx.x, cb4 = blockIdx.y;
    int tid = threadIdx.x;
    for (int i = tid; i < L*NH; i += 256)
        sWv[i] = g_Wv[(i >> 6)*(D*NH) + d*NH + (i & 63)];
    for (int i = tid; i < 4096; i += 256) {
        int b = i >> 8, t = i & 255;
        sU[t*UP + b] = g_xT[(d*BSZ + b)*SEQ + (cb4 << 8) + t];
    }
    __syncthreads();

    int nq = tid & 15, cbq = tid >> 4;
    int n0 = nq << 2;
    int cc = cbq >> 2, b0 = (cbq & 3) << 2;
    float acc[4][4];
    #pragma unroll
    for (int bi = 0; bi < 4; bi++)
        #pragma unroll
        for (int ni = 0; ni < 4; ni++) acc[bi][ni] = 0.f;

    #pragma unroll 8
    for (int j = 0; j < L; j++) {
        float4 w = *(const float4*)&sWv[j*NH + n0];
        float4 u = *(const float4*)&sU[(cc*64 + j)*UP + b0];
        acc[0][0] += u.x*w.x; acc[0][1] += u.x*w.y; acc[0][2] += u.x*w.z; acc[0][3] += u.x*w.w;
        acc[1][0] += u.y*w.x; acc[1][1] += u.y*w.y; acc[1][2] += u.y*w.z; acc[1][3] += u.y*w.w;
        acc[2][0] += u.z*w.x; acc[2][1] += u.z*w.y; acc[2][2] += u.z*w.z; acc[2][3] += u.z*w.w;
        acc[3][0] += u.w*w.x; acc[3][1] += u.w*w.y; acc[3][2] += u.w*w.z; acc[3][3] += u.w*w.w;
    }
    int c = (cb4 << 2) + cc;
    #pragma unroll
    for (int bi = 0; bi < 4; bi++) {
        float4 o = make_float4(acc[bi][0], acc[bi][1], acc[bi][2], acc[bi][3]);
        *(float4*)&g_G[((c*D + d)*BSZ + b0 + bi)*NH + n0] = o;
    }
}

// ---------------- K2a: group sums, 4 pairs per warp (halved sM traffic, doubled MLP) -----
__global__ __launch_bounds__(256) void k_S()
{
    __shared__ float2 sM[NH*32];       // sM[m*32+n] = { M[n][m], M[n+32][m] }
    int tid = threadIdx.x, lane = tid & 31, w = tid >> 5;
    for (int i = tid; i < NH*32; i += 256) {
        int m = i >> 5, nn = i & 31;
        sM[i] = make_float2(g_MpT[m*NH + nn], g_MpT[m*NH + nn + 32]);
    }
    __syncthreads();

    int wg = blockIdx.x*8 + w;         // 0..2047
    int g  = wg >> 8;                  // group 0..7 (256 warps per group)
    int qa = (wg & 255)*4;             // 4 pairs per warp
    float h0[4], h1[4];
    #pragma unroll
    for (int p = 0; p < 4; p++) { h0[p] = 0.f; h1[p] = 0.f; }

    for (int k = 0; k < GS; k++) {
        int c = g*GS + k;
        float gg0[4], gg1[4];
        #pragma unroll
        for (int p = 0; p < 4; p++) {
            int base = (c*1024 + qa + p)*64;
            gg0[p] = g_G[base + lane];  gg1[p] = g_G[base + 32 + lane];
        }
        float n0[4], n1[4];
        #pragma unroll
        for (int p = 0; p < 4; p++) { n0[p] = 0.f; n1[p] = 0.f; }
        #pragma unroll
        for (int m = 0; m < 32; m++) {
            float2 mm = sM[m*32 + lane];
            #pragma unroll
            for (int p = 0; p < 4; p++) {
                float hm = __shfl_sync(0xffffffffu, h0[p], m);
                n0[p] += mm.x*hm; n1[p] += mm.y*hm;
            }
        }
        #pragma unroll
        for (int m = 0; m < 32; m++) {
            float2 mm = sM[(m + 32)*32 + lane];
            #pragma unroll
            for (int p = 0; p < 4; p++) {
                float hm = __shfl_sync(0xffffffffu, h1[p], m);
                n0[p] += mm.x*hm; n1[p] += mm.y*hm;
            }
        }
        #pragma unroll
        for (int p = 0; p < 4; p++) { h0[p] = n0[p] + gg0[p]; h1[p] = n1[p] + gg1[p]; }
    }
    #pragma unroll
    for (int p = 0; p < 4; p++) {
        int sb = (g*1024 + qa + p)*64;
        g_S[sb + lane] = h0[p];  g_S[sb + 32 + lane] = h1[p];
    }
}

// ---------------- K2b: carry scan C[g+1] = M^8 C[g] + S[g] (8 seq steps, 1024 pairs) -----
__global__ __launch_bounds__(256) void k_C()
{
    __shared__ float2 sM8[NH*32];      // { M8[n][m], M8[n+32][m] }
    int tid = threadIdx.x, lane = tid & 31, w = tid >> 5;
    for (int i = tid; i < NH*32; i += 256) {
        int m = i >> 5, nn = i & 31;
        sM8[i] = make_float2(g_M8T[m*NH + nn], g_M8T[m*NH + nn + 32]);
    }
    __syncthreads();

    int pair = blockIdx.x*8 + w;       // 0..1023 (warp per pair)
    float c0 = 0.f, c1 = 0.f;
    for (int g = 0; g < NG; g++) {
        int base = (g*1024 + pair)*64;
        g_C[base + lane] = c0;  g_C[base + 32 + lane] = c1;
        float s0 = g_S[base + lane], s1 = g_S[base + 32 + lane];
        float n0 = 0.f, n1 = 0.f;
        #pragma unroll
        for (int m = 0; m < 32; m++) {
            float hm = __shfl_sync(0xffffffffu, c0, m);
            float2 mm = sM8[m*32 + lane];
            n0 += mm.x*hm; n1 += mm.y*hm;
        }
        #pragma unroll
        for (int m = 0; m < 32; m++) {
            float hm = __shfl_sync(0xffffffffu, c1, m);
            float2 mm = sM8[(m + 32)*32 + lane];
            n0 += mm.x*hm; n1 += mm.y*hm;
        }
        c0 = n0 + s0; c1 = n1 + s1;
    }
}

// ---------------- K2c: rescan seeded with carries, 4 pairs per warp ----------------------
__global__ __launch_bounds__(256) void k_A2()
{
    __shared__ float2 sM[NH*32];       // sM[m*32+n] = { M[n][m], M[n+32][m] }
    int tid = threadIdx.x, lane = tid & 31, w = tid >> 5;
    for (int i = tid; i < NH*32; i += 256) {
        int m = i >> 5, nn = i & 31;
        sM[i] = make_float2(g_MpT[m*NH + nn], g_MpT[m*NH + nn + 32]);
    }
    __syncthreads();

    int wg = blockIdx.x*8 + w;         // 0..2047
    int g  = wg >> 8;
    int qa = (wg & 255)*4;
    float h0[4], h1[4];
    #pragma unroll
    for (int p = 0; p < 4; p++) {
        int cb = (g*1024 + qa + p)*64;
        h0[p] = g_C[cb + lane];  h1[p] = g_C[cb + 32 + lane];
    }
    for (int k = 0; k < GS; k++) {
        int c = g*GS + k;
        #pragma unroll
        for (int p = 0; p < 4; p++) {
            int base = (c*1024 + qa + p)*64;
            g_H[base + lane] = h0[p];  g_H[base + 32 + lane] = h1[p];
        }
        if (k == GS-1) break;
        float gg0[4], gg1[4];
        #pragma unroll
        for (int p = 0; p < 4; p++) {
            int base = (c*1024 + qa + p)*64;
            gg0[p] = g_G[base + lane];  gg1[p] = g_G[base + 32 + lane];
        }
        float n0[4], n1[4];
        #pragma unroll
        for (int p = 0; p < 4; p++) { n0[p] = 0.f; n1[p] = 0.f; }
        #pragma unroll
        for (int m = 0; m < 32; m++) {
            float2 mm = sM[m*32 + lane];
            #pragma unroll
            for (int p = 0; p < 4; p++) {
                float hm = __shfl_sync(0xffffffffu, h0[p], m);
                n0[p] += mm.x*hm; n1[p] += mm.y*hm;
            }
        }
        #pragma unroll
        for (int m = 0; m < 32; m++) {
            float2 mm = sM[(m + 32)*32 + lane];
            #pragma unroll
            for (int p = 0; p < 4; p++) {
                float hm = __shfl_sync(0xffffffffu, h1[p], m);
                n0[p] += mm.x*hm; n1[p] += mm.y*hm;
            }
        }
        #pragma unroll
        for (int p = 0; p < 4; p++) { h0[p] = n0[p] + gg0[p]; h1[p] = n1[p] + gg1[p]; }
    }
}

// ---------------- K3: y = cross-term (Rp·H) + intra-chunk conv (R8-proven, 4 chunks) -----
#define RPP 66
__global__ __launch_bounds__(256) void k_y()
{
    __shared__ float sRpT[NH*RPP];     // sRpT[n*RPP + r] = Rp[r+1][d][n]
    __shared__ float sKp[128];         // zero-padded causal kernel
    __shared__ float sH[2][NH*UP];     // per-half chunk state [n*UP + b]
    __shared__ float sUc[2][L*UP];     // per-half chunk input [j*UP + b]
    int d = blockIdx.x, c0 = blockIdx.y << 2, tid = threadIdx.x;
    int half = tid >> 7, ltid = tid & 127;

    for (int i = tid; i < 4096; i += 256) {
        int r = i >> 6, n = i & 63;
        sRpT[n*RPP + r] = g_Rp[((r + 1)*D + d)*NH + n];
    }
    if (tid < 127) sKp[tid] = (tid < 63) ? 0.f : g_Keff[(tid - 63)*D + d];
    __syncthreads();

    for (int pass = 0; pass < 2; pass++) {
        int c = c0 + pass*2 + half;
        for (int i = ltid; i < 1024; i += 128) {
            int b = i >> 6, n = i & 63;
            sH[half][n*UP + b] = g_H[((c*D + d)*BSZ + b)*NH + n];
        }
        for (int i = ltid; i < 1024; i += 128) {
            int b = i >> 6, j = i & 63;
            sUc[half][j*UP + b] = g_xT[(d*BSZ + b)*SEQ + (c << 6) + j];
        }
        __syncthreads();

        int rq = ltid & 31, bq = ltid >> 5;
        int r0 = rq << 1, b0 = bq << 2;
        float acc[2][4];
        #pragma unroll
        for (int ri = 0; ri < 2; ri++)
            #pragma unroll
            for (int bi = 0; bi < 4; bi++) acc[ri][bi] = 0.f;

        #pragma unroll 8
        for (int n = 0; n < NH; n++) {             // cross term
            float2 rv = *(const float2*)&sRpT[n*RPP + r0];
            float4 h  = *(const float4*)&sH[half][n*UP + b0];
            acc[0][0] += rv.x*h.x; acc[0][1] += rv.x*h.y; acc[0][2] += rv.x*h.z; acc[0][3] += rv.x*h.w;
            acc[1][0] += rv.y*h.x; acc[1][1] += rv.y*h.y; acc[1][2] += rv.y*h.z; acc[1][3] += rv.y*h.w;
        }
        #pragma unroll 8
        for (int j = 0; j < L; j++) {              // intra-chunk conv (zero-padded kernel)
            float k0 = sKp[63 + r0 - j];
            float k1 = sKp[64 + r0 - j];
            float4 u = *(const float4*)&sUc[half][j*UP + b0];
            acc[0][0] += k0*u.x; acc[0][1] += k0*u.y; acc[0][2] += k0*u.z; acc[0][3] += k0*u.w;
            acc[1][0] += k1*u.x; acc[1][1] += k1*u.y; acc[1][2] += k1*u.z; acc[1][3] += k1*u.w;
        }
        #pragma unroll
        for (int bi = 0; bi < 4; bi++) {
            float2 o = make_float2(acc[0][bi], acc[1][bi]);
            *(float2*)&g_y[(d*BSZ + b0 + bi)*SEQ + (c << 6) + r0] = o;
        }
        __syncthreads();
    }
}

// ---------------- K4: out[b][t][:] = y[:, b, t]·W^T + bias -------------------------------
#define WP 68
__global__ __launch_bounds__(256) void k_mix(const float* __restrict__ Wm,
                                             const float* __restrict__ bias,
                                             float* __restrict__ out)
{
    __shared__ float sW[D*WP];         // sW[d*WP + o] = W[o][d]
    __shared__ float sy[D*WP];         // sy[d*WP + tt]
    int b = blockIdx.x, t0 = blockIdx.y << 6, tid = threadIdx.x;
    for (int i = tid; i < 4096; i += 256) {
        int o = i >> 6, dd = i & 63;
        sW[dd*WP + o] = Wm[o*D + dd];
    }
    for (int i = tid; i < 4096; i += 256) {
        int dd = i >> 6, tt = i & 63;
        sy[dd*WP + tt] = g_y[(dd*BSZ + b)*SEQ + t0 + tt];
    }
    __syncthreads();

    int tq = tid & 15, oq = tid >> 4;
    int tl0 = tq << 2, o0 = oq << 2;
    float acc[4][4];
    #pragma unroll
    for (int ti = 0; ti < 4; ti++)
        #pragma unroll
        for (int oi = 0; oi < 4; oi++) acc[ti][oi] = 0.f;

    #pragma unroll 8
    for (int dd = 0; dd < D; dd++) {
        float4 wv = *(const float4*)&sW[dd*WP + o0];
        float4 yv = *(const float4*)&sy[dd*WP + tl0];
        acc[0][0] += yv.x*wv.x; acc[0][1] += yv.x*wv.y; acc[0][2] += yv.x*wv.z; acc[0][3] += yv.x*wv.w;
        acc[1][0] += yv.y*wv.x; acc[1][1] += yv.y*wv.y; acc[1][2] += yv.y*wv.z; acc[1][3] += yv.y*wv.w;
        acc[2][0] += yv.z*wv.x; acc[2][1] += yv.z*wv.y; acc[2][2] += yv.z*wv.z; acc[2][3] += yv.z*wv.w;
        acc[3][0] += yv.w*wv.x; acc[3][1] += yv.w*wv.y; acc[3][2] += yv.w*wv.z; acc[3][3] += yv.w*wv.w;
    }
    float4 bv = *(const float4*)&bias[o0];
    #pragma unroll
    for (int ti = 0; ti < 4; ti++) {
        float4 o = make_float4(acc[ti][0] + bv.x, acc[ti][1] + bv.y,
                               acc[ti][2] + bv.z, acc[ti][3] + bv.w);
        *(float4*)&out[(b*SEQ + t0 + tl0 + ti)*DOUT + o0] = o;
    }
}

// ---------------- launch -----------------------------------------------------------------
extern "C" void kernel_launch(void* const* d_in, const int* in_sizes, int n_in,
                              void* d_out, int out_size)
{
    const float* x    = (const float*)d_in[0];
    const float* dA   = (const float*)d_in[1];
    const float* dB   = (const float*)d_in[2];
    const float* Cp   = (const float*)d_in[3];
    const float* Dp   = (const float*)d_in[4];
    const float* Wm   = (const float*)d_in[5];
    const float* bias = (const float*)d_in[6];
    float* out = (float*)d_out;

    k_tables   <<<128, 64>>>(dA, dB, Cp, Dp);
    k_pow      <<<64, 64>>>();
    k_transpose<<<dim3(BSZ, SEQ/64), 256>>>(x);
    k_G        <<<dim3(D, NC/4), 256>>>();
    k_S        <<<256, 256>>>();
    k_C        <<<128, 256>>>();
    k_A2       <<<256, 256>>>();
    k_y        <<<dim3(D, NC/4), 256>>>();
    k_mix      <<<dim3(BSZ, SEQ/64), 256>>>(Wm, bias, out);
}